// round 16
// baseline (speedup 1.0000x reference)
#include <cuda_runtime.h>
#include <cuda_fp16.h>

#define NN 50000
#define NED 800000
#define NPAD 50176   // 256*196

// ---- scratch layout (float slots) ----
constexpr long F_ROWPTR = 0;          // ints, 50240
constexpr long F_CURSOR = 50240;      // ints, 50176 (histogram -> cursor)
constexpr long F_EIDX   = 100416;     // ints, 800000
constexpr long F_GATE   = 900416;     // halves in CSR order: NE*64 -> 25.6M float slots
constexpr long F_VSUM   = 26500416;   // [NN][64]
constexpr long F_VMAX   = 29700416;   // [NN][64]
constexpr long F_S      = 32900416;   // [NN][256] states s1..s4
constexpr long F_VC     = 45700416;   // [NN][64]
constexpr long F_AB     = 48900416;   // [NN][128]
constexpr long F_EN     = 55300416;   // halves: NE*64 -> 25.6M float slots
constexpr long F_STAT   = 106500416;  // 256
constexpr long F_COEF   = 106500672;  // 256
constexpr long F_SRCC   = 106500928;  // ints, 800000 (src in CSR order)
constexpr long F_TOTAL  = 107300928;

__device__ float g_buf[F_TOTAL];

__device__ __forceinline__ float lrelu(float x) { return fmaxf(x, 0.2f * x); }
__device__ __forceinline__ float sigf(float x) { return 1.f / (1.f + __expf(-x)); }
__device__ __forceinline__ unsigned f2tf32(float x) {
    unsigned r; asm("cvt.rna.tf32.f32 %0, %1;" : "=r"(r) : "f"(x)); return r;
}
__device__ __forceinline__ void mma_tf32(float* c, unsigned a0, unsigned a1,
                                         unsigned a2, unsigned a3,
                                         unsigned b0, unsigned b1) {
    asm("mma.sync.aligned.m16n8k8.row.col.f32.tf32.tf32.f32 "
        "{%0,%1,%2,%3}, {%4,%5,%6,%7}, {%8,%9}, {%0,%1,%2,%3};"
        : "+f"(c[0]), "+f"(c[1]), "+f"(c[2]), "+f"(c[3])
        : "r"(a0), "r"(a1), "r"(a2), "r"(a3), "r"(b0), "r"(b1));
}

// ---------- CSR build ----------
__global__ void k_hist(const int* __restrict__ dst, int* __restrict__ cnt) {
    int e = blockIdx.x * 256 + threadIdx.x;
    atomicAdd(cnt + __ldg(dst + e), 1);
}

__global__ void k_scan(int* __restrict__ cnt_cursor, int* __restrict__ rowptr,
                       float* __restrict__ stat) {
    __shared__ int part[257];
    int t = threadIdx.x;
    stat[t] = 0.f;   // fused stat zeroing (256 entries)
    int base = t * 196;
    int s = 0;
    for (int i = 0; i < 196; i++) s += cnt_cursor[base + i];
    part[t + 1] = s;
    if (t == 0) part[0] = 0;
    __syncthreads();
    if (t == 0) {
        int r = 0;
        for (int i = 1; i <= 256; i++) { r += part[i]; part[i] = r; }
    }
    __syncthreads();
    int run = part[t];
    for (int i = 0; i < 196; i++) {
        int c = cnt_cursor[base + i];
        rowptr[base + i] = run;
        cnt_cursor[base + i] = run;  // becomes cursor
        run += c;
    }
}

__global__ void k_scatter(const int* __restrict__ dst, const int* __restrict__ src,
                          int* __restrict__ cursor, int* __restrict__ eidx,
                          int* __restrict__ src_csr) {
    int e = blockIdx.x * 256 + threadIdx.x;
    int p = atomicAdd(cursor + __ldg(dst + e), 1);
    eidx[p] = e;
    src_csr[p] = __ldg(src + e);
}

// ---------- gate = sigmoid(E[eidx[p]]) stored fp16 in CSR order ----------
__global__ void k_gate_csr(const float4* __restrict__ E4, const int* __restrict__ eidx,
                           uint4* __restrict__ gate) {
    long t = (long)blockIdx.x * 256 + threadIdx.x;  // NED*8 threads
    int p = (int)(t >> 3), q = (int)(t & 7);
    int e = __ldg(eidx + p);
    float4 a = __ldg(E4 + (long)e * 16 + q * 2);
    float4 b = __ldg(E4 + (long)e * 16 + q * 2 + 1);
    union { uint4 u; __half2 h[4]; } o;
    o.h[0] = __floats2half2_rn(sigf(a.x), sigf(a.y));
    o.h[1] = __floats2half2_rn(sigf(a.z), sigf(a.w));
    o.h[2] = __floats2half2_rn(sigf(b.x), sigf(b.y));
    o.h[3] = __floats2half2_rn(sigf(b.z), sigf(b.w));
    gate[(long)p * 8 + q] = o.u;
}

// ---------- fused gather-aggregate + combine: one warp per node ----------
__global__ void k_agg(const float* __restrict__ X, int xp, const float* __restrict__ V,
                      const int* __restrict__ rowptr, const int* __restrict__ src_csr,
                      const __half2* __restrict__ gate,
                      float* __restrict__ vsum, float* __restrict__ vmax,
                      float* __restrict__ S, int outoff,
                      const float* __restrict__ wa, const float* __restrict__ wb,
                      int pass) {
    int n = (blockIdx.x * 256 + threadIdx.x) >> 5;
    int lane = threadIdx.x & 31;
    if (n >= NN) return;
    int r0 = __ldg(rowptr + n), r1 = __ldg(rowptr + n + 1);
    float deg = (float)(r1 - r0);
    float ninf = __int_as_float(0xff800000);
    float2 sum = {0.f, 0.f}, mx = {ninf, ninf};
    int i = r0;
    for (; i + 2 <= r1; i += 2) {
        int s0 = __ldg(src_csr + i);
        int s1 = __ldg(src_csr + i + 1);
        float2 g0 = __half22float2(__ldg(gate + (long)i * 32 + lane));
        float2 g1 = __half22float2(__ldg(gate + (long)(i + 1) * 32 + lane));
        float2 x0 = *(const float2*)(X + (long)s0 * xp + 2 * lane);
        float2 x1 = *(const float2*)(X + (long)s1 * xp + 2 * lane);
        float m0 = x0.x * g0.x, m1 = x0.y * g0.y;
        float m2 = x1.x * g1.x, m3 = x1.y * g1.y;
        sum.x += m0; sum.y += m1;
        mx.x = fmaxf(mx.x, m0); mx.y = fmaxf(mx.y, m1);
        sum.x += m2; sum.y += m3;
        mx.x = fmaxf(mx.x, m2); mx.y = fmaxf(mx.y, m3);
    }
    if (i < r1) {
        int s0 = __ldg(src_csr + i);
        float2 g0 = __half22float2(__ldg(gate + (long)i * 32 + lane));
        float2 x0 = *(const float2*)(X + (long)s0 * xp + 2 * lane);
        float m0 = x0.x * g0.x, m1 = x0.y * g0.y;
        sum.x += m0; sum.y += m1;
        mx.x = fmaxf(mx.x, m0); mx.y = fmaxf(mx.y, m1);
    }
    if (deg == 0.f) { mx.x = 0.f; mx.y = 0.f; }
    float rdeg = 1.f / fmaxf(deg, 1.f);
    long o = (long)n * 64 + 2 * lane;
    float2 vn = *(const float2*)(V + o);
    float w1 = __ldg(wa + 1), w2 = __ldg(wa + 2);
    float c = __ldg(wa + 3) * rdeg + __ldg(wa + 4);
    float2 out;
    if (pass == 1) {
        *(float2*)(vsum + o) = sum;
        *(float2*)(vmax + o) = mx;
        out.x = w1 * vn.x + w2 * mx.x + c * sum.x;
        out.y = w1 * vn.y + w2 * mx.y + c * sum.y;
    } else {
        float2 vs = *(const float2*)(vsum + o);
        float2 vm = *(const float2*)(vmax + o);
        float2 xn = *(const float2*)(X + (long)n * xp + 2 * lane);
        float u1 = __ldg(wb + 1), u2 = __ldg(wb + 2);
        float c2 = __ldg(wb + 3) * rdeg + __ldg(wb + 4);
        out.x = w1 * vn.x + w2 * vm.x + c * vs.x + u1 * xn.x + u2 * mx.x + c2 * sum.x;
        out.y = w1 * vn.y + w2 * vm.y + c * vs.y + u1 * xn.y + u2 * mx.y + c2 * sum.y;
    }
    *(float2*)(S + (long)n * 256 + outoff + 2 * lane) = out;
}

// ---------- Vc = S[N,256] @ W_cat[256,64] + b_cat  (+ shfl col stats) ----------
__global__ void k_gemm_vc(const float* __restrict__ S, const float* __restrict__ Wc,
                          const float* __restrict__ bc, float* __restrict__ Vc,
                          float* __restrict__ stat) {
    extern __shared__ float sm[];
    float* Ws = sm;               // [256][72]
    float* bs = sm + 256 * 72;    // [64]
    float* cs = bs + 64;          // [64]
    float* cq = cs + 64;          // [64]
    for (int i = threadIdx.x; i < 256 * 64; i += 256) {
        int k = i >> 6, j = i & 63;
        Ws[k * 72 + j] = __uint_as_float(f2tf32(Wc[i]));
    }
    if (threadIdx.x < 64) { bs[threadIdx.x] = bc[threadIdx.x]; cs[threadIdx.x] = 0.f; }
    else if (threadIdx.x < 128) cq[threadIdx.x - 64] = 0.f;
    __syncthreads();
    int warp = threadIdx.x >> 5, lane = threadIdx.x & 31;
    int g = lane >> 2, tg = lane & 3;
    int r0 = (blockIdx.x * 8 + warp) * 16;
    if (r0 < NN) {
        float acc[8][4];
#pragma unroll
        for (int i = 0; i < 8; i++) acc[i][0] = acc[i][1] = acc[i][2] = acc[i][3] = 0.f;
#pragma unroll 4
        for (int ks = 0; ks < 32; ks++) {
            int k0 = ks * 8;
            const float* Ar = S + (long)(r0 + g) * 256 + k0 + tg;
            unsigned a0 = f2tf32(__ldg(Ar));
            unsigned a2 = f2tf32(__ldg(Ar + 4));
            unsigned a1 = f2tf32(__ldg(Ar + 8 * 256));
            unsigned a3 = f2tf32(__ldg(Ar + 8 * 256 + 4));
#pragma unroll
            for (int nt = 0; nt < 8; nt++) {
                unsigned b0 = __float_as_uint(Ws[(k0 + tg) * 72 + nt * 8 + g]);
                unsigned b1 = __float_as_uint(Ws[(k0 + tg + 4) * 72 + nt * 8 + g]);
                mma_tf32(acc[nt], a0, a1, a2, a3, b0, b1);
            }
        }
#pragma unroll
        for (int nt = 0; nt < 8; nt++) {
            int nc = nt * 8 + 2 * tg;
            float2 o0 = {acc[nt][0] + bs[nc], acc[nt][1] + bs[nc + 1]};
            float2 o1 = {acc[nt][2] + bs[nc], acc[nt][3] + bs[nc + 1]};
            *(float2*)(Vc + (long)(r0 + g) * 64 + nc) = o0;
            *(float2*)(Vc + (long)(r0 + g + 8) * 64 + nc) = o1;
            float sx = o0.x + o1.x, sy = o0.y + o1.y;
            float qx = o0.x * o0.x + o1.x * o1.x, qy = o0.y * o0.y + o1.y * o1.y;
#pragma unroll
            for (int m = 4; m < 32; m <<= 1) {
                sx += __shfl_xor_sync(0xffffffffu, sx, m);
                sy += __shfl_xor_sync(0xffffffffu, sy, m);
                qx += __shfl_xor_sync(0xffffffffu, qx, m);
                qy += __shfl_xor_sync(0xffffffffu, qy, m);
            }
            if (lane < 4) {
                atomicAdd(&cs[nc], sx);
                atomicAdd(&cs[nc + 1], sy);
                atomicAdd(&cq[nc], qx);
                atomicAdd(&cq[nc + 1], qy);
            }
        }
    }
    __syncthreads();
    if (threadIdx.x < 64) atomicAdd(stat + threadIdx.x, cs[threadIdx.x]);
    else if (threadIdx.x < 128) atomicAdd(stat + threadIdx.x, cq[threadIdx.x - 64]);
}

// ---------- AB[N][128] = Vc @ [W_S rows 0..63 | W_S rows 128..191] ----------
__global__ void k_gemm_ab(const float* __restrict__ Vc, const float* __restrict__ W_S,
                          float* __restrict__ AB) {
    __shared__ float Ws[64 * 136];
    for (int i = threadIdx.x; i < 64 * 128; i += 256) {
        int k = i >> 7, j = i & 127;
        float w = (j < 64) ? W_S[k * 64 + j] : W_S[(128 + k) * 64 + (j - 64)];
        Ws[k * 136 + j] = __uint_as_float(f2tf32(w));
    }
    __syncthreads();
    int warp = threadIdx.x >> 5, lane = threadIdx.x & 31;
    int g = lane >> 2, tg = lane & 3;
    int r0 = (blockIdx.x * 8 + warp) * 16;
    if (r0 >= NN) return;
    float acc[16][4];
#pragma unroll
    for (int i = 0; i < 16; i++) acc[i][0] = acc[i][1] = acc[i][2] = acc[i][3] = 0.f;
#pragma unroll
    for (int ks = 0; ks < 8; ks++) {
        int k0 = ks * 8;
        const float* Ar = Vc + (long)(r0 + g) * 64 + k0 + tg;
        unsigned a0 = f2tf32(__ldg(Ar));
        unsigned a2 = f2tf32(__ldg(Ar + 4));
        unsigned a1 = f2tf32(__ldg(Ar + 8 * 64));
        unsigned a3 = f2tf32(__ldg(Ar + 8 * 64 + 4));
#pragma unroll
        for (int nt = 0; nt < 16; nt++) {
            unsigned b0 = __float_as_uint(Ws[(k0 + tg) * 136 + nt * 8 + g]);
            unsigned b1 = __float_as_uint(Ws[(k0 + tg + 4) * 136 + nt * 8 + g]);
            mma_tf32(acc[nt], a0, a1, a2, a3, b0, b1);
        }
    }
#pragma unroll
    for (int nt = 0; nt < 16; nt++) {
        int nc = nt * 8 + 2 * tg;
        float2 o0 = {acc[nt][0], acc[nt][1]};
        float2 o1 = {acc[nt][2], acc[nt][3]};
        *(float2*)(AB + (long)(r0 + g) * 128 + nc) = o0;
        *(float2*)(AB + (long)(r0 + g + 8) * 128 + nc) = o1;
    }
}

// ---------- En = leaky(E)@W_S[64:128] + A[src] + B[dst] + b_S ----------
// stores En as fp16; BN column stats accumulated in fp32 via shfl tree
__global__ void k_gemm_en(const float* __restrict__ E, const int* __restrict__ src,
                          const int* __restrict__ dst, const float* __restrict__ W_S,
                          const float* __restrict__ bS, const float* __restrict__ AB,
                          __half* __restrict__ En, float* __restrict__ stat) {
    __shared__ float Ws[64 * 72];
    __shared__ float bsh[64];
    __shared__ float cs[64], cq[64];
    for (int i = threadIdx.x; i < 64 * 64; i += 256) {
        int k = i >> 6, j = i & 63;
        Ws[k * 72 + j] = __uint_as_float(f2tf32(W_S[(64 + k) * 64 + j]));
    }
    if (threadIdx.x < 64) { bsh[threadIdx.x] = bS[threadIdx.x]; cs[threadIdx.x] = 0.f; }
    else if (threadIdx.x < 128) cq[threadIdx.x - 64] = 0.f;
    __syncthreads();
    int warp = threadIdx.x >> 5, lane = threadIdx.x & 31;
    int g = lane >> 2, tg = lane & 3;
    int e0 = (blockIdx.x * 8 + warp) * 16;
    // hoisted gather indices: lets the epilogue AB loads issue immediately
    int sa = __ldg(src + e0 + g), sb = __ldg(src + e0 + 8 + g);
    int da = __ldg(dst + e0 + g), db = __ldg(dst + e0 + 8 + g);
    float acc[8][4];
#pragma unroll
    for (int i = 0; i < 8; i++) acc[i][0] = acc[i][1] = acc[i][2] = acc[i][3] = 0.f;
    const float* Er0 = E + (long)(e0 + g) * 64;
    const float* Er1 = E + (long)(e0 + g + 8) * 64;
#pragma unroll 2
    for (int ks = 0; ks < 8; ks++) {
        int k0 = ks * 8;
        unsigned a0 = f2tf32(lrelu(__ldg(Er0 + k0 + tg)));
        unsigned a1 = f2tf32(lrelu(__ldg(Er1 + k0 + tg)));
        unsigned a2 = f2tf32(lrelu(__ldg(Er0 + k0 + tg + 4)));
        unsigned a3 = f2tf32(lrelu(__ldg(Er1 + k0 + tg + 4)));
#pragma unroll
        for (int nt = 0; nt < 8; nt++) {
            unsigned b0 = __float_as_uint(Ws[(k0 + tg) * 72 + nt * 8 + g]);
            unsigned b1 = __float_as_uint(Ws[(k0 + tg + 4) * 72 + nt * 8 + g]);
            mma_tf32(acc[nt], a0, a1, a2, a3, b0, b1);
        }
    }
#pragma unroll
    for (int nt = 0; nt < 8; nt++) {
        int nc = nt * 8 + 2 * tg;
        float2 A0 = *(const float2*)(AB + (long)sa * 128 + nc);
        float2 B0 = *(const float2*)(AB + (long)da * 128 + 64 + nc);
        float2 A1 = *(const float2*)(AB + (long)sb * 128 + nc);
        float2 B1 = *(const float2*)(AB + (long)db * 128 + 64 + nc);
        float2 o0 = {acc[nt][0] + A0.x + B0.x + bsh[nc], acc[nt][1] + A0.y + B0.y + bsh[nc + 1]};
        float2 o1 = {acc[nt][2] + A1.x + B1.x + bsh[nc], acc[nt][3] + A1.y + B1.y + bsh[nc + 1]};
        *(__half2*)(En + (long)(e0 + g) * 64 + nc) = __floats2half2_rn(o0.x, o0.y);
        *(__half2*)(En + (long)(e0 + g + 8) * 64 + nc) = __floats2half2_rn(o1.x, o1.y);
        // column stats: reduce over the row dimension (g) with shfl, then 4-lane atomic
        float sx = o0.x + o1.x, sy = o0.y + o1.y;
        float qx = o0.x * o0.x + o1.x * o1.x, qy = o0.y * o0.y + o1.y * o1.y;
#pragma unroll
        for (int m = 4; m < 32; m <<= 1) {
            sx += __shfl_xor_sync(0xffffffffu, sx, m);
            sy += __shfl_xor_sync(0xffffffffu, sy, m);
            qx += __shfl_xor_sync(0xffffffffu, qx, m);
            qy += __shfl_xor_sync(0xffffffffu, qy, m);
        }
        if (lane < 4) {
            atomicAdd(&cs[nc], sx);
            atomicAdd(&cs[nc + 1], sy);
            atomicAdd(&cq[nc], qx);
            atomicAdd(&cq[nc + 1], qy);
        }
    }
    __syncthreads();
    if (threadIdx.x < 64) atomicAdd(stat + 128 + threadIdx.x, cs[threadIdx.x]);
    else if (threadIdx.x < 128) atomicAdd(stat + 192 + threadIdx.x - 64, cq[threadIdx.x - 64]);
}

__global__ void k_final(const float* __restrict__ stat, const float* __restrict__ gV,
                        const float* __restrict__ bV, const float* __restrict__ gE,
                        const float* __restrict__ bE, float* __restrict__ coef) {
    int c = threadIdx.x;  // 64
    float muV = stat[c] * (1.f / NN);
    float vV = stat[64 + c] * (1.f / NN) - muV * muV;
    float aV = gV[c] * rsqrtf(vV + 1e-5f);
    coef[c] = aV;
    coef[64 + c] = bV[c] - aV * muV;
    float muE = stat[128 + c] * (1.f / NED);
    float vE = stat[192 + c] * (1.f / NED) - muE * muE;
    float aE = gE[c] * rsqrtf(vE + 1e-5f);
    coef[128 + c] = aE;
    coef[192 + c] = bE[c] - aE * muE;
}

__global__ void k_vo(const float4* __restrict__ Vc4, const float4* __restrict__ V4,
                     const float* __restrict__ coef, float4* __restrict__ out) {
    long t = (long)blockIdx.x * 256 + threadIdx.x;  // NN*16
    int c0 = (t & 15) * 4;
    float4 vc = Vc4[t], v = V4[t];
    float4 o;
    o.x = lrelu(coef[c0 + 0] * vc.x + coef[64 + c0 + 0]) + v.x;
    o.y = lrelu(coef[c0 + 1] * vc.y + coef[64 + c0 + 1]) + v.y;
    o.z = lrelu(coef[c0 + 2] * vc.z + coef[64 + c0 + 2]) + v.z;
    o.w = lrelu(coef[c0 + 3] * vc.w + coef[64 + c0 + 3]) + v.w;
    out[t] = o;
}

__global__ void k_eo(const uint2* __restrict__ En2, const float4* __restrict__ E4,
                     const float* __restrict__ coef, float4* __restrict__ out) {
    long t = (long)blockIdx.x * 256 + threadIdx.x;  // NE*16
    int c0 = (t & 15) * 4;
    uint2 enp = __ldcs(En2 + t);
    __half2 h0 = *reinterpret_cast<__half2*>(&enp.x);
    __half2 h1 = *reinterpret_cast<__half2*>(&enp.y);
    float2 ea = __half22float2(h0);
    float2 eb = __half22float2(h1);
    float4 e = __ldcs(E4 + t);
    float4 o;
    o.x = lrelu(coef[128 + c0 + 0] * ea.x + coef[192 + c0 + 0]) + e.x;
    o.y = lrelu(coef[128 + c0 + 1] * ea.y + coef[192 + c0 + 1]) + e.y;
    o.z = lrelu(coef[128 + c0 + 2] * eb.x + coef[192 + c0 + 2]) + e.z;
    o.w = lrelu(coef[128 + c0 + 3] * eb.y + coef[192 + c0 + 3]) + e.w;
    out[t] = o;
}

extern "C" void kernel_launch(void* const* d_in, const int* in_sizes, int n_in,
                              void* d_out, int out_size) {
    const float* V = (const float*)d_in[0];
    const float* E = (const float*)d_in[1];
    const int* src = (const int*)d_in[2];
    const int* dst = (const int*)d_in[3];
    const float* weight = (const float*)d_in[4];
    const float* W_cat = (const float*)d_in[5];
    const float* b_cat = (const float*)d_in[6];
    const float* W_S = (const float*)d_in[7];
    const float* b_S = (const float*)d_in[8];
    const float* gV = (const float*)d_in[9];
    const float* bV = (const float*)d_in[10];
    const float* gE = (const float*)d_in[11];
    const float* bE = (const float*)d_in[12];
    float* out = (float*)d_out;

    float* B;
    cudaGetSymbolAddress((void**)&B, g_buf);
    int* rowptr = (int*)(B + F_ROWPTR);
    int* cursor = (int*)(B + F_CURSOR);
    int* eidx = (int*)(B + F_EIDX);
    int* src_csr = (int*)(B + F_SRCC);
    float* gate = B + F_GATE;
    float* vsum = B + F_VSUM;
    float* vmax = B + F_VMAX;
    float* S = B + F_S;
    float* Vc = B + F_VC;
    float* AB = B + F_AB;
    __half* En = (__half*)(B + F_EN);
    float* stat = B + F_STAT;
    float* coef = B + F_COEF;

    cudaMemsetAsync(cursor, 0, NPAD * sizeof(int));

    k_hist<<<NED / 256, 256>>>(dst, cursor);
    k_scan<<<1, 256>>>(cursor, rowptr, stat);
    k_scatter<<<NED / 256, 256>>>(dst, src, cursor, eidx, src_csr);
    k_gate_csr<<<NED * 8 / 256, 256>>>((const float4*)E, eidx, (uint4*)gate);

    const __half2* gh = (const __half2*)gate;
    // pass 1: aggregate V -> (vsum,vmax), s1 = mixed(V, w0)
    k_agg<<<6250, 256>>>(V, 64, V, rowptr, src_csr, gh, vsum, vmax, S, 0,
                         weight + 0, weight + 0, 1);
    // pass 2: s2 = mixed(V,w1) + mixed(s1,w2)
    k_agg<<<6250, 256>>>(S + 0, 256, V, rowptr, src_csr, gh, vsum, vmax, S, 64,
                         weight + 5, weight + 10, 2);
    // pass 3: s3 = mixed(V,w3) + mixed(s2,w4)
    k_agg<<<6250, 256>>>(S + 64, 256, V, rowptr, src_csr, gh, vsum, vmax, S, 128,
                         weight + 15, weight + 20, 2);
    // pass 4: s4 = mixed(V,w5) + mixed(s3,w6)
    k_agg<<<6250, 256>>>(S + 128, 256, V, rowptr, src_csr, gh, vsum, vmax, S, 192,
                         weight + 25, weight + 30, 2);

    cudaFuncSetAttribute(k_gemm_vc, cudaFuncAttributeMaxDynamicSharedMemorySize, 74496);
    k_gemm_vc<<<391, 256, 74496>>>(S, W_cat, b_cat, Vc, stat);
    k_gemm_ab<<<391, 256>>>(Vc, W_S, AB);
    k_gemm_en<<<6250, 256>>>(E, src, dst, W_S, b_S, AB, En, stat);
    k_final<<<1, 64>>>(stat, gV, bV, gE, bE, coef);
    k_vo<<<NN * 16 / 256, 256>>>((const float4*)Vc, (const float4*)V, coef, (float4*)out);
    k_eo<<<NED * 16 / 256, 256>>>((const uint2*)En, (const float4*)E, coef,
                                  (float4*)(out + (long)NN * 64));
}

// round 17
// speedup vs baseline: 1.3973x; 1.3973x over previous
#include <cuda_runtime.h>
#include <cuda_fp16.h>

#define NN 50000
#define NED 800000
#define NPAD 50176   // 256*196

// ---- scratch layout (float slots) ----
constexpr long F_ROWPTR = 0;          // ints, 50240
constexpr long F_CURSOR = 50240;      // ints, 50176 (histogram -> cursor)
constexpr long F_EIDX   = 100416;     // ints, 800000
constexpr long F_GATE   = 900416;     // halves in CSR order: NE*64 -> 25.6M float slots
constexpr long F_VSUM   = 26500416;   // half2 [NN][32] -> 1.6M float slots
constexpr long F_VMAX   = 29700416;   // half2 [NN][32]
constexpr long F_S      = 32900416;   // [NN][256] states s1..s4 (fp32)
constexpr long F_VC     = 45700416;   // [NN][64]
constexpr long F_AB     = 48900416;   // [NN][128]
constexpr long F_EN     = 55300416;   // halves: NE*64 -> 25.6M float slots
constexpr long F_STAT   = 106500416;  // 256
constexpr long F_COEF   = 106500672;  // 256
constexpr long F_SRCC   = 106500928;  // ints, 800000 (src in CSR order)
constexpr long F_TOTAL  = 107300928;

__device__ float g_buf[F_TOTAL];

__device__ __forceinline__ float lrelu(float x) { return fmaxf(x, 0.2f * x); }
__device__ __forceinline__ float sigf(float x) { return 1.f / (1.f + __expf(-x)); }
__device__ __forceinline__ unsigned f2tf32(float x) {
    unsigned r; asm("cvt.rna.tf32.f32 %0, %1;" : "=r"(r) : "f"(x)); return r;
}
__device__ __forceinline__ void mma_tf32(float* c, unsigned a0, unsigned a1,
                                         unsigned a2, unsigned a3,
                                         unsigned b0, unsigned b1) {
    asm("mma.sync.aligned.m16n8k8.row.col.f32.tf32.tf32.f32 "
        "{%0,%1,%2,%3}, {%4,%5,%6,%7}, {%8,%9}, {%0,%1,%2,%3};"
        : "+f"(c[0]), "+f"(c[1]), "+f"(c[2]), "+f"(c[3])
        : "r"(a0), "r"(a1), "r"(a2), "r"(a3), "r"(b0), "r"(b1));
}

// ---------- CSR build ----------
__global__ void k_hist(const int* __restrict__ dst, int* __restrict__ cnt) {
    int e = blockIdx.x * 256 + threadIdx.x;
    atomicAdd(cnt + __ldg(dst + e), 1);
}

__global__ void k_scan(int* __restrict__ cnt_cursor, int* __restrict__ rowptr,
                       float* __restrict__ stat) {
    __shared__ int part[257];
    int t = threadIdx.x;
    stat[t] = 0.f;   // fused stat zeroing (256 entries)
    int base = t * 196;
    int s = 0;
    for (int i = 0; i < 196; i++) s += cnt_cursor[base + i];
    part[t + 1] = s;
    if (t == 0) part[0] = 0;
    __syncthreads();
    if (t == 0) {
        int r = 0;
        for (int i = 1; i <= 256; i++) { r += part[i]; part[i] = r; }
    }
    __syncthreads();
    int run = part[t];
    for (int i = 0; i < 196; i++) {
        int c = cnt_cursor[base + i];
        rowptr[base + i] = run;
        cnt_cursor[base + i] = run;  // becomes cursor
        run += c;
    }
}

__global__ void k_scatter(const int* __restrict__ dst, const int* __restrict__ src,
                          int* __restrict__ cursor, int* __restrict__ eidx,
                          int* __restrict__ src_csr) {
    int e = blockIdx.x * 256 + threadIdx.x;
    int p = atomicAdd(cursor + __ldg(dst + e), 1);
    eidx[p] = e;
    src_csr[p] = __ldg(src + e);
}

// ---------- gate = sigmoid(E[eidx[p]]) stored fp16 in CSR order ----------
__global__ void k_gate_csr(const float4* __restrict__ E4, const int* __restrict__ eidx,
                           uint4* __restrict__ gate) {
    long t = (long)blockIdx.x * 256 + threadIdx.x;  // NED*8 threads
    int p = (int)(t >> 3), q = (int)(t & 7);
    int e = __ldg(eidx + p);
    float4 a = __ldg(E4 + (long)e * 16 + q * 2);
    float4 b = __ldg(E4 + (long)e * 16 + q * 2 + 1);
    union { uint4 u; __half2 h[4]; } o;
    o.h[0] = __floats2half2_rn(sigf(a.x), sigf(a.y));
    o.h[1] = __floats2half2_rn(sigf(a.z), sigf(a.w));
    o.h[2] = __floats2half2_rn(sigf(b.x), sigf(b.y));
    o.h[3] = __floats2half2_rn(sigf(b.z), sigf(b.w));
    gate[(long)p * 8 + q] = o.u;
}

// ---------- fused gather-aggregate + combine: one warp per node ----------
// gate read with __ldcs (streaming, no reuse); vsum/vmax cached as fp16
__global__ void k_agg(const float* __restrict__ X, int xp, const float* __restrict__ V,
                      const int* __restrict__ rowptr, const int* __restrict__ src_csr,
                      const __half2* __restrict__ gate,
                      __half2* __restrict__ vsum, __half2* __restrict__ vmax,
                      float* __restrict__ S, int outoff,
                      const float* __restrict__ wa, const float* __restrict__ wb,
                      int pass) {
    int n = (blockIdx.x * 256 + threadIdx.x) >> 5;
    int lane = threadIdx.x & 31;
    if (n >= NN) return;
    int r0 = __ldg(rowptr + n), r1 = __ldg(rowptr + n + 1);
    float deg = (float)(r1 - r0);
    float ninf = __int_as_float(0xff800000);
    float2 sum = {0.f, 0.f}, mx = {ninf, ninf};
    int i = r0;
    for (; i + 2 <= r1; i += 2) {
        int s0 = __ldg(src_csr + i);
        int s1 = __ldg(src_csr + i + 1);
        float2 g0 = __half22float2(__ldcs(gate + (long)i * 32 + lane));
        float2 g1 = __half22float2(__ldcs(gate + (long)(i + 1) * 32 + lane));
        float2 x0 = *(const float2*)(X + (long)s0 * xp + 2 * lane);
        float2 x1 = *(const float2*)(X + (long)s1 * xp + 2 * lane);
        float m0 = x0.x * g0.x, m1 = x0.y * g0.y;
        float m2 = x1.x * g1.x, m3 = x1.y * g1.y;
        sum.x += m0; sum.y += m1;
        mx.x = fmaxf(mx.x, m0); mx.y = fmaxf(mx.y, m1);
        sum.x += m2; sum.y += m3;
        mx.x = fmaxf(mx.x, m2); mx.y = fmaxf(mx.y, m3);
    }
    if (i < r1) {
        int s0 = __ldg(src_csr + i);
        float2 g0 = __half22float2(__ldcs(gate + (long)i * 32 + lane));
        float2 x0 = *(const float2*)(X + (long)s0 * xp + 2 * lane);
        float m0 = x0.x * g0.x, m1 = x0.y * g0.y;
        sum.x += m0; sum.y += m1;
        mx.x = fmaxf(mx.x, m0); mx.y = fmaxf(mx.y, m1);
    }
    if (deg == 0.f) { mx.x = 0.f; mx.y = 0.f; }
    float rdeg = 1.f / fmaxf(deg, 1.f);
    long o = (long)n * 64 + 2 * lane;
    long oh = (long)n * 32 + lane;
    float2 vn = *(const float2*)(V + o);
    float w1 = __ldg(wa + 1), w2 = __ldg(wa + 2);
    float c = __ldg(wa + 3) * rdeg + __ldg(wa + 4);
    float2 out;
    if (pass == 1) {
        vsum[oh] = __floats2half2_rn(sum.x, sum.y);
        vmax[oh] = __floats2half2_rn(mx.x, mx.y);
        out.x = w1 * vn.x + w2 * mx.x + c * sum.x;
        out.y = w1 * vn.y + w2 * mx.y + c * sum.y;
    } else {
        float2 vs = __half22float2(vsum[oh]);
        float2 vm = __half22float2(vmax[oh]);
        float2 xn = *(const float2*)(X + (long)n * xp + 2 * lane);
        float u1 = __ldg(wb + 1), u2 = __ldg(wb + 2);
        float c2 = __ldg(wb + 3) * rdeg + __ldg(wb + 4);
        out.x = w1 * vn.x + w2 * vm.x + c * vs.x + u1 * xn.x + u2 * mx.x + c2 * sum.x;
        out.y = w1 * vn.y + w2 * vm.y + c * vs.y + u1 * xn.y + u2 * mx.y + c2 * sum.y;
    }
    *(float2*)(S + (long)n * 256 + outoff + 2 * lane) = out;
}

// ---------- Vc = S[N,256] @ W_cat[256,64] + b_cat  (+ shfl col stats) ----------
__global__ void k_gemm_vc(const float* __restrict__ S, const float* __restrict__ Wc,
                          const float* __restrict__ bc, float* __restrict__ Vc,
                          float* __restrict__ stat) {
    extern __shared__ float sm[];
    float* Ws = sm;               // [256][72]
    float* bs = sm + 256 * 72;    // [64]
    float* cs = bs + 64;          // [64]
    float* cq = cs + 64;          // [64]
    for (int i = threadIdx.x; i < 256 * 64; i += 256) {
        int k = i >> 6, j = i & 63;
        Ws[k * 72 + j] = __uint_as_float(f2tf32(Wc[i]));
    }
    if (threadIdx.x < 64) { bs[threadIdx.x] = bc[threadIdx.x]; cs[threadIdx.x] = 0.f; }
    else if (threadIdx.x < 128) cq[threadIdx.x - 64] = 0.f;
    __syncthreads();
    int warp = threadIdx.x >> 5, lane = threadIdx.x & 31;
    int g = lane >> 2, tg = lane & 3;
    int r0 = (blockIdx.x * 8 + warp) * 16;
    if (r0 < NN) {
        float acc[8][4];
#pragma unroll
        for (int i = 0; i < 8; i++) acc[i][0] = acc[i][1] = acc[i][2] = acc[i][3] = 0.f;
#pragma unroll 4
        for (int ks = 0; ks < 32; ks++) {
            int k0 = ks * 8;
            const float* Ar = S + (long)(r0 + g) * 256 + k0 + tg;
            unsigned a0 = f2tf32(__ldg(Ar));
            unsigned a2 = f2tf32(__ldg(Ar + 4));
            unsigned a1 = f2tf32(__ldg(Ar + 8 * 256));
            unsigned a3 = f2tf32(__ldg(Ar + 8 * 256 + 4));
#pragma unroll
            for (int nt = 0; nt < 8; nt++) {
                unsigned b0 = __float_as_uint(Ws[(k0 + tg) * 72 + nt * 8 + g]);
                unsigned b1 = __float_as_uint(Ws[(k0 + tg + 4) * 72 + nt * 8 + g]);
                mma_tf32(acc[nt], a0, a1, a2, a3, b0, b1);
            }
        }
#pragma unroll
        for (int nt = 0; nt < 8; nt++) {
            int nc = nt * 8 + 2 * tg;
            float2 o0 = {acc[nt][0] + bs[nc], acc[nt][1] + bs[nc + 1]};
            float2 o1 = {acc[nt][2] + bs[nc], acc[nt][3] + bs[nc + 1]};
            *(float2*)(Vc + (long)(r0 + g) * 64 + nc) = o0;
            *(float2*)(Vc + (long)(r0 + g + 8) * 64 + nc) = o1;
            float sx = o0.x + o1.x, sy = o0.y + o1.y;
            float qx = o0.x * o0.x + o1.x * o1.x, qy = o0.y * o0.y + o1.y * o1.y;
#pragma unroll
            for (int m = 4; m < 32; m <<= 1) {
                sx += __shfl_xor_sync(0xffffffffu, sx, m);
                sy += __shfl_xor_sync(0xffffffffu, sy, m);
                qx += __shfl_xor_sync(0xffffffffu, qx, m);
                qy += __shfl_xor_sync(0xffffffffu, qy, m);
            }
            if (lane < 4) {
                atomicAdd(&cs[nc], sx);
                atomicAdd(&cs[nc + 1], sy);
                atomicAdd(&cq[nc], qx);
                atomicAdd(&cq[nc + 1], qy);
            }
        }
    }
    __syncthreads();
    if (threadIdx.x < 64) atomicAdd(stat + threadIdx.x, cs[threadIdx.x]);
    else if (threadIdx.x < 128) atomicAdd(stat + threadIdx.x, cq[threadIdx.x - 64]);
}

// ---------- AB[N][128] = Vc @ [W_S rows 0..63 | W_S rows 128..191] ----------
__global__ void k_gemm_ab(const float* __restrict__ Vc, const float* __restrict__ W_S,
                          float* __restrict__ AB) {
    __shared__ float Ws[64 * 136];
    for (int i = threadIdx.x; i < 64 * 128; i += 256) {
        int k = i >> 7, j = i & 127;
        float w = (j < 64) ? W_S[k * 64 + j] : W_S[(128 + k) * 64 + (j - 64)];
        Ws[k * 136 + j] = __uint_as_float(f2tf32(w));
    }
    __syncthreads();
    int warp = threadIdx.x >> 5, lane = threadIdx.x & 31;
    int g = lane >> 2, tg = lane & 3;
    int r0 = (blockIdx.x * 8 + warp) * 16;
    if (r0 >= NN) return;
    float acc[16][4];
#pragma unroll
    for (int i = 0; i < 16; i++) acc[i][0] = acc[i][1] = acc[i][2] = acc[i][3] = 0.f;
#pragma unroll
    for (int ks = 0; ks < 8; ks++) {
        int k0 = ks * 8;
        const float* Ar = Vc + (long)(r0 + g) * 64 + k0 + tg;
        unsigned a0 = f2tf32(__ldg(Ar));
        unsigned a2 = f2tf32(__ldg(Ar + 4));
        unsigned a1 = f2tf32(__ldg(Ar + 8 * 64));
        unsigned a3 = f2tf32(__ldg(Ar + 8 * 64 + 4));
#pragma unroll
        for (int nt = 0; nt < 16; nt++) {
            unsigned b0 = __float_as_uint(Ws[(k0 + tg) * 136 + nt * 8 + g]);
            unsigned b1 = __float_as_uint(Ws[(k0 + tg + 4) * 136 + nt * 8 + g]);
            mma_tf32(acc[nt], a0, a1, a2, a3, b0, b1);
        }
    }
#pragma unroll
    for (int nt = 0; nt < 16; nt++) {
        int nc = nt * 8 + 2 * tg;
        float2 o0 = {acc[nt][0], acc[nt][1]};
        float2 o1 = {acc[nt][2], acc[nt][3]};
        *(float2*)(AB + (long)(r0 + g) * 128 + nc) = o0;
        *(float2*)(AB + (long)(r0 + g + 8) * 128 + nc) = o1;
    }
}

// ---------- En = leaky(E)@W_S[64:128] + A[src] + B[dst] + b_S ----------
// stores En as fp16; BN column stats accumulated in fp32 via shfl tree
__global__ void k_gemm_en(const float* __restrict__ E, const int* __restrict__ src,
                          const int* __restrict__ dst, const float* __restrict__ W_S,
                          const float* __restrict__ bS, const float* __restrict__ AB,
                          __half* __restrict__ En, float* __restrict__ stat) {
    __shared__ float Ws[64 * 72];
    __shared__ float bsh[64];
    __shared__ float cs[64], cq[64];
    for (int i = threadIdx.x; i < 64 * 64; i += 256) {
        int k = i >> 6, j = i & 63;
        Ws[k * 72 + j] = __uint_as_float(f2tf32(W_S[(64 + k) * 64 + j]));
    }
    if (threadIdx.x < 64) { bsh[threadIdx.x] = bS[threadIdx.x]; cs[threadIdx.x] = 0.f; }
    else if (threadIdx.x < 128) cq[threadIdx.x - 64] = 0.f;
    __syncthreads();
    int warp = threadIdx.x >> 5, lane = threadIdx.x & 31;
    int g = lane >> 2, tg = lane & 3;
    int e0 = (blockIdx.x * 8 + warp) * 16;
    // hoisted gather indices: lets the epilogue AB loads issue immediately
    int sa = __ldg(src + e0 + g), sb = __ldg(src + e0 + 8 + g);
    int da = __ldg(dst + e0 + g), db = __ldg(dst + e0 + 8 + g);
    float acc[8][4];
#pragma unroll
    for (int i = 0; i < 8; i++) acc[i][0] = acc[i][1] = acc[i][2] = acc[i][3] = 0.f;
    const float* Er0 = E + (long)(e0 + g) * 64;
    const float* Er1 = E + (long)(e0 + g + 8) * 64;
#pragma unroll 2
    for (int ks = 0; ks < 8; ks++) {
        int k0 = ks * 8;
        unsigned a0 = f2tf32(lrelu(__ldg(Er0 + k0 + tg)));
        unsigned a1 = f2tf32(lrelu(__ldg(Er1 + k0 + tg)));
        unsigned a2 = f2tf32(lrelu(__ldg(Er0 + k0 + tg + 4)));
        unsigned a3 = f2tf32(lrelu(__ldg(Er1 + k0 + tg + 4)));
#pragma unroll
        for (int nt = 0; nt < 8; nt++) {
            unsigned b0 = __float_as_uint(Ws[(k0 + tg) * 72 + nt * 8 + g]);
            unsigned b1 = __float_as_uint(Ws[(k0 + tg + 4) * 72 + nt * 8 + g]);
            mma_tf32(acc[nt], a0, a1, a2, a3, b0, b1);
        }
    }
#pragma unroll
    for (int nt = 0; nt < 8; nt++) {
        int nc = nt * 8 + 2 * tg;
        float2 A0 = *(const float2*)(AB + (long)sa * 128 + nc);
        float2 B0 = *(const float2*)(AB + (long)da * 128 + 64 + nc);
        float2 A1 = *(const float2*)(AB + (long)sb * 128 + nc);
        float2 B1 = *(const float2*)(AB + (long)db * 128 + 64 + nc);
        float2 o0 = {acc[nt][0] + A0.x + B0.x + bsh[nc], acc[nt][1] + A0.y + B0.y + bsh[nc + 1]};
        float2 o1 = {acc[nt][2] + A1.x + B1.x + bsh[nc], acc[nt][3] + A1.y + B1.y + bsh[nc + 1]};
        *(__half2*)(En + (long)(e0 + g) * 64 + nc) = __floats2half2_rn(o0.x, o0.y);
        *(__half2*)(En + (long)(e0 + g + 8) * 64 + nc) = __floats2half2_rn(o1.x, o1.y);
        // column stats: reduce over the row dimension (g) with shfl, then 4-lane atomic
        float sx = o0.x + o1.x, sy = o0.y + o1.y;
        float qx = o0.x * o0.x + o1.x * o1.x, qy = o0.y * o0.y + o1.y * o1.y;
#pragma unroll
        for (int m = 4; m < 32; m <<= 1) {
            sx += __shfl_xor_sync(0xffffffffu, sx, m);
            sy += __shfl_xor_sync(0xffffffffu, sy, m);
            qx += __shfl_xor_sync(0xffffffffu, qx, m);
            qy += __shfl_xor_sync(0xffffffffu, qy, m);
        }
        if (lane < 4) {
            atomicAdd(&cs[nc], sx);
            atomicAdd(&cs[nc + 1], sy);
            atomicAdd(&cq[nc], qx);
            atomicAdd(&cq[nc + 1], qy);
        }
    }
    __syncthreads();
    if (threadIdx.x < 64) atomicAdd(stat + 128 + threadIdx.x, cs[threadIdx.x]);
    else if (threadIdx.x < 128) atomicAdd(stat + 192 + threadIdx.x - 64, cq[threadIdx.x - 64]);
}

__global__ void k_final(const float* __restrict__ stat, const float* __restrict__ gV,
                        const float* __restrict__ bV, const float* __restrict__ gE,
                        const float* __restrict__ bE, float* __restrict__ coef) {
    int c = threadIdx.x;  // 64
    float muV = stat[c] * (1.f / NN);
    float vV = stat[64 + c] * (1.f / NN) - muV * muV;
    float aV = gV[c] * rsqrtf(vV + 1e-5f);
    coef[c] = aV;
    coef[64 + c] = bV[c] - aV * muV;
    float muE = stat[128 + c] * (1.f / NED);
    float vE = stat[192 + c] * (1.f / NED) - muE * muE;
    float aE = gE[c] * rsqrtf(vE + 1e-5f);
    coef[128 + c] = aE;
    coef[192 + c] = bE[c] - aE * muE;
}

__global__ void k_vo(const float4* __restrict__ Vc4, const float4* __restrict__ V4,
                     const float* __restrict__ coef, float4* __restrict__ out) {
    long t = (long)blockIdx.x * 256 + threadIdx.x;  // NN*16
    int c0 = (t & 15) * 4;
    float4 vc = Vc4[t], v = V4[t];
    float4 o;
    o.x = lrelu(coef[c0 + 0] * vc.x + coef[64 + c0 + 0]) + v.x;
    o.y = lrelu(coef[c0 + 1] * vc.y + coef[64 + c0 + 1]) + v.y;
    o.z = lrelu(coef[c0 + 2] * vc.z + coef[64 + c0 + 2]) + v.z;
    o.w = lrelu(coef[c0 + 3] * vc.w + coef[64 + c0 + 3]) + v.w;
    out[t] = o;
}

__global__ void k_eo(const uint2* __restrict__ En2, const float4* __restrict__ E4,
                     const float* __restrict__ coef, float4* __restrict__ out) {
    long t = (long)blockIdx.x * 256 + threadIdx.x;  // NE*16
    int c0 = (t & 15) * 4;
    uint2 enp = __ldcs(En2 + t);
    __half2 h0 = *reinterpret_cast<__half2*>(&enp.x);
    __half2 h1 = *reinterpret_cast<__half2*>(&enp.y);
    float2 ea = __half22float2(h0);
    float2 eb = __half22float2(h1);
    float4 e = __ldcs(E4 + t);
    float4 o;
    o.x = lrelu(coef[128 + c0 + 0] * ea.x + coef[192 + c0 + 0]) + e.x;
    o.y = lrelu(coef[128 + c0 + 1] * ea.y + coef[192 + c0 + 1]) + e.y;
    o.z = lrelu(coef[128 + c0 + 2] * eb.x + coef[192 + c0 + 2]) + e.z;
    o.w = lrelu(coef[128 + c0 + 3] * eb.y + coef[192 + c0 + 3]) + e.w;
    out[t] = o;
}

extern "C" void kernel_launch(void* const* d_in, const int* in_sizes, int n_in,
                              void* d_out, int out_size) {
    const float* V = (const float*)d_in[0];
    const float* E = (const float*)d_in[1];
    const int* src = (const int*)d_in[2];
    const int* dst = (const int*)d_in[3];
    const float* weight = (const float*)d_in[4];
    const float* W_cat = (const float*)d_in[5];
    const float* b_cat = (const float*)d_in[6];
    const float* W_S = (const float*)d_in[7];
    const float* b_S = (const float*)d_in[8];
    const float* gV = (const float*)d_in[9];
    const float* bV = (const float*)d_in[10];
    const float* gE = (const float*)d_in[11];
    const float* bE = (const float*)d_in[12];
    float* out = (float*)d_out;

    float* B;
    cudaGetSymbolAddress((void**)&B, g_buf);
    int* rowptr = (int*)(B + F_ROWPTR);
    int* cursor = (int*)(B + F_CURSOR);
    int* eidx = (int*)(B + F_EIDX);
    int* src_csr = (int*)(B + F_SRCC);
    float* gate = B + F_GATE;
    __half2* vsum = (__half2*)(B + F_VSUM);
    __half2* vmax = (__half2*)(B + F_VMAX);
    float* S = B + F_S;
    float* Vc = B + F_VC;
    float* AB = B + F_AB;
    __half* En = (__half*)(B + F_EN);
    float* stat = B + F_STAT;
    float* coef = B + F_COEF;

    cudaMemsetAsync(cursor, 0, NPAD * sizeof(int));

    k_hist<<<NED / 256, 256>>>(dst, cursor);
    k_scan<<<1, 256>>>(cursor, rowptr, stat);
    k_scatter<<<NED / 256, 256>>>(dst, src, cursor, eidx, src_csr);
    k_gate_csr<<<NED * 8 / 256, 256>>>((const float4*)E, eidx, (uint4*)gate);

    const __half2* gh = (const __half2*)gate;
    // pass 1: aggregate V -> (vsum,vmax), s1 = mixed(V, w0)
    k_agg<<<6250, 256>>>(V, 64, V, rowptr, src_csr, gh, vsum, vmax, S, 0,
                         weight + 0, weight + 0, 1);
    // pass 2: s2 = mixed(V,w1) + mixed(s1,w2)
    k_agg<<<6250, 256>>>(S + 0, 256, V, rowptr, src_csr, gh, vsum, vmax, S, 64,
                         weight + 5, weight + 10, 2);
    // pass 3: s3 = mixed(V,w3) + mixed(s2,w4)
    k_agg<<<6250, 256>>>(S + 64, 256, V, rowptr, src_csr, gh, vsum, vmax, S, 128,
                         weight + 15, weight + 20, 2);
    // pass 4: s4 = mixed(V,w5) + mixed(s3,w6)
    k_agg<<<6250, 256>>>(S + 128, 256, V, rowptr, src_csr, gh, vsum, vmax, S, 192,
                         weight + 25, weight + 30, 2);

    cudaFuncSetAttribute(k_gemm_vc, cudaFuncAttributeMaxDynamicSharedMemorySize, 74496);
    k_gemm_vc<<<391, 256, 74496>>>(S, W_cat, b_cat, Vc, stat);
    k_gemm_ab<<<391, 256>>>(Vc, W_S, AB);
    k_gemm_en<<<6250, 256>>>(E, src, dst, W_S, b_S, AB, En, stat);
    k_final<<<1, 64>>>(stat, gV, bV, gE, bE, coef);
    k_vo<<<NN * 16 / 256, 256>>>((const float4*)Vc, (const float4*)V, coef, (float4*)out);
    k_eo<<<NED * 16 / 256, 256>>>((const uint2*)En, (const float4*)E, coef,
                                  (float4*)(out + (long)NN * 64));
}